// round 17
// baseline (speedup 1.0000x reference)
#include <cuda_runtime.h>
#include <cstdint>
#include <cstddef>

#define Dm   512
#define Bm_  16
#define Sm   4096
#define G3   1536
#define NGRP 4           // independent scan groups (4 batches each)
#define GCTA 32          // CTAs per group
#define BPG  4           // batches per group
#define DPC  16          // h-dims per CTA (48 Wh columns)
#define NBLK (NGRP * GCTA)
#define NTHR 256

// Scratch (device globals: allocation-free per harness rules)
__device__ float    g_gi[(size_t)Bm_ * Sm * G3];   // [b][t][1536]
__device__ float    g_rnn[(size_t)Bm_ * Sm * Dm];  // [b][t][512]
__device__ float    g_h[2][NGRP][Dm][BPG];         // ping-pong H per group
__device__ unsigned g_cnt[NGRP * 32];              // per-group counters, 128B apart

__global__ void init_state()
{
    int tid = blockIdx.x * blockDim.x + threadIdx.x;
    if (tid < NGRP * 32) g_cnt[tid] = 0u;
    if (tid < NGRP * Dm * BPG) ((float*)g_h)[tid] = 0.f;   // zero g_h[0]
}

__device__ __forceinline__ unsigned ld_acq(const unsigned* p)
{
    unsigned v;
    asm volatile("ld.acquire.gpu.u32 %0, [%1];" : "=r"(v) : "l"(p) : "memory");
    return v;
}

__device__ __forceinline__ float cvt_tf32(float x)
{
    unsigned u;
    asm("cvt.rna.tf32.f32 %0, %1;" : "=r"(u) : "f"(x));
    return __uint_as_float(u);
}

__device__ __forceinline__ void ffma2(unsigned long long& d,
                                      unsigned long long a,
                                      unsigned long long b)
{
    asm("fma.rn.f32x2 %0, %1, %2, %0;" : "+l"(d) : "l"(a), "l"(b));
}

// ---------------------------------------------------------------------------
// tf32 tensor-core GEMM: C[M,N] = A[M,K] @ B[K,N] + bias[N]   (R14, proven)
// ---------------------------------------------------------------------------
__global__ void __launch_bounds__(256) tf32_gemm_bias(
    const float* __restrict__ A, const float* __restrict__ Bmat,
    const float* __restrict__ bias, float* __restrict__ C,
    int M, int N, int K)
{
    __shared__ float As[32 * 132];   // [k][m]
    __shared__ float Bs[32 * 72];    // [k][n]

    const int tid = threadIdx.x;
    const int warp = tid >> 5, lane = tid & 31;
    const int wm = warp >> 2, wn = warp & 3;
    const int m0 = blockIdx.y * 128;
    const int n0 = blockIdx.x * 64;

    const int gid = lane >> 2;
    const int qid = lane & 3;

    const int a_row = tid >> 2;
    const int a_kq  = (tid & 3) * 4;

    float d[4][2][4];
#pragma unroll
    for (int mt = 0; mt < 4; ++mt)
#pragma unroll
        for (int nt = 0; nt < 2; ++nt)
#pragma unroll
            for (int i = 0; i < 4; ++i) d[mt][nt][i] = 0.f;

    for (int k0 = 0; k0 < K; k0 += 32) {
#pragma unroll
        for (int rr = 0; rr < 2; ++rr) {
#pragma unroll
            for (int kk = 0; kk < 2; ++kk) {
                int row = a_row + rr * 64;
                int kq  = a_kq + kk * 16;
                float4 v = *(const float4*)(A + (size_t)(m0 + row) * K + k0 + kq);
                As[(kq + 0) * 132 + row] = cvt_tf32(v.x);
                As[(kq + 1) * 132 + row] = cvt_tf32(v.y);
                As[(kq + 2) * 132 + row] = cvt_tf32(v.z);
                As[(kq + 3) * 132 + row] = cvt_tf32(v.w);
            }
        }
        {
            int r  = tid >> 4;
            int cq = (tid & 15) * 4;
#pragma unroll
            for (int i = 0; i < 2; ++i) {
                int row = r + i * 16;
                float4 v = *(const float4*)(Bmat + (size_t)(k0 + row) * N + n0 + cq);
                float4 tv;
                tv.x = cvt_tf32(v.x); tv.y = cvt_tf32(v.y);
                tv.z = cvt_tf32(v.z); tv.w = cvt_tf32(v.w);
                *(float4*)&Bs[row * 72 + cq] = tv;
            }
        }
        __syncthreads();

#pragma unroll
        for (int ks = 0; ks < 4; ++ks) {
            const int kb = ks * 8;
            unsigned bf0[2], bf1[2];
#pragma unroll
            for (int nt = 0; nt < 2; ++nt) {
                int n = wn * 16 + nt * 8 + gid;
                bf0[nt] = __float_as_uint(Bs[(kb + qid) * 72 + n]);
                bf1[nt] = __float_as_uint(Bs[(kb + qid + 4) * 72 + n]);
            }
#pragma unroll
            for (int mt = 0; mt < 4; ++mt) {
                int m = wm * 64 + mt * 16 + gid;
                unsigned a0 = __float_as_uint(As[(kb + qid) * 132 + m]);
                unsigned a1 = __float_as_uint(As[(kb + qid) * 132 + m + 8]);
                unsigned a2 = __float_as_uint(As[(kb + qid + 4) * 132 + m]);
                unsigned a3 = __float_as_uint(As[(kb + qid + 4) * 132 + m + 8]);
#pragma unroll
                for (int nt = 0; nt < 2; ++nt) {
                    asm volatile(
                        "mma.sync.aligned.m16n8k8.row.col.f32.tf32.tf32.f32 "
                        "{%0,%1,%2,%3}, {%4,%5,%6,%7}, {%8,%9}, {%0,%1,%2,%3};"
                        : "+f"(d[mt][nt][0]), "+f"(d[mt][nt][1]),
                          "+f"(d[mt][nt][2]), "+f"(d[mt][nt][3])
                        : "r"(a0), "r"(a1), "r"(a2), "r"(a3),
                          "r"(bf0[nt]), "r"(bf1[nt]));
                }
            }
        }
        __syncthreads();
    }

#pragma unroll
    for (int mt = 0; mt < 4; ++mt) {
        int m = m0 + wm * 64 + mt * 16 + gid;
#pragma unroll
        for (int nt = 0; nt < 2; ++nt) {
            int n = n0 + wn * 16 + nt * 8 + qid * 2;
            float2 bv = *(const float2*)(bias + n);
            float2 o0 = make_float2(d[mt][nt][0] + bv.x, d[mt][nt][1] + bv.y);
            float2 o1 = make_float2(d[mt][nt][2] + bv.x, d[mt][nt][3] + bv.y);
            *(float2*)(C + (size_t)m * N + n) = o0;
            *(float2*)(C + (size_t)(m + 8) * N + n) = o1;
        }
    }
}

// ---------------------------------------------------------------------------
// Persistent GRU scan: weights PREPACKED as (w[k],w[k+256]) u64 registers
// (48/thread, no per-step MOV packing). H staged as hP[b][k2]=(h[k2],h[k2+256]).
// gi prefetched one step ahead; hold in register; early-arrival barrier.
// 4 independent groups x 32 CTAs; CTA owns 16 dims x 4 batches.
// ---------------------------------------------------------------------------
__global__ void __launch_bounds__(NTHR, 1) gru_scan(
    const float* __restrict__ Wh, const float* __restrict__ bhn)
{
    __shared__ unsigned long long hP[BPG][256];  // (h[k2],h[k2+256]) per batch
    __shared__ float red[48 * BPG * 8];          // [cc][b][8] 8-way partials

    const int tid = threadIdx.x;
    const int bid = blockIdx.x;
    const int grp = bid >> 5;
    const int cid = bid & 31;
    const int d0  = cid * DPC;
    const int b0  = grp * BPG;

    const int warp = tid >> 5, lane = tid & 31;

    // ---- one-time: prepack this thread's 96 weights into 48 u64 ----
    // col cc = 6*warp + i; k-pair = (lane+32j, lane+32j+256), j=0..7
    unsigned long long w2[6][8];
#pragma unroll
    for (int i = 0; i < 6; ++i) {
        int cc = 6 * warp + i;
        int gate = cc >> 4, dim = cc & 15;
        const float* wp = Wh + (size_t)gate * Dm + d0 + dim;
#pragma unroll
        for (int j = 0; j < 8; ++j) {
            int klo = lane + 32 * j;
            float wl = __ldg(wp + (size_t)klo * G3);
            float wh = __ldg(wp + (size_t)(klo + 256) * G3);
            asm("mov.b64 %0, {%1, %2};" : "=l"(w2[i][j]) : "f"(wl), "f"(wh));
        }
    }

    const int dloc = tid >> 2, gb = tid & 3;   // gate mapping (tid<64)
    float my_bhn = 0.f;
    if (tid < 64) my_bhn = bhn[d0 + dloc];

    unsigned* cnt = &g_cnt[grp * 32];
    unsigned target = 0;

    // hold register (h(0)=0) and gi prefetch for t=0
    float hold = 0.f;
    float gir = 0.f, giz = 0.f, gin = 0.f;
    if (tid < 64) {
        const float* gp = g_gi + ((size_t)(b0 + gb) * Sm + 0) * G3 + d0 + dloc;
        gir = __ldg(gp); giz = __ldg(gp + Dm); gin = __ldg(gp + 2 * Dm);
    }

    for (int t = 0; t < Sm; ++t) {
        const float* Hc = &g_h[t & 1][grp][0][0];
        float* Hn = &g_h[(t & 1) ^ 1][grp][0][0];

        // ---- fill hP: thread tid handles k2 = tid (k-pair deinterleave) ----
        {
            float4 lo, hi;
            asm volatile("ld.global.cg.v4.f32 {%0,%1,%2,%3}, [%4];"
                         : "=f"(lo.x), "=f"(lo.y), "=f"(lo.z), "=f"(lo.w)
                         : "l"(&Hc[tid * BPG]));
            asm volatile("ld.global.cg.v4.f32 {%0,%1,%2,%3}, [%4];"
                         : "=f"(hi.x), "=f"(hi.y), "=f"(hi.z), "=f"(hi.w)
                         : "l"(&Hc[(tid + 256) * BPG]));
            unsigned long long p;
            asm("mov.b64 %0, {%1, %2};" : "=l"(p) : "f"(lo.x), "f"(hi.x));
            hP[0][tid] = p;
            asm("mov.b64 %0, {%1, %2};" : "=l"(p) : "f"(lo.y), "f"(hi.y));
            hP[1][tid] = p;
            asm("mov.b64 %0, {%1, %2};" : "=l"(p) : "f"(lo.z), "f"(hi.z));
            hP[2][tid] = p;
            asm("mov.b64 %0, {%1, %2};" : "=l"(p) : "f"(lo.w), "f"(hi.w));
            hP[3][tid] = p;
        }
        __syncthreads();

        // ---- k-loop: prepacked weights x k-paired H, no MOVs ----
        unsigned long long acc[6][4];
#pragma unroll
        for (int i = 0; i < 6; ++i)
#pragma unroll
            for (int b = 0; b < 4; ++b) acc[i][b] = 0ull;

#pragma unroll
        for (int j = 0; j < 8; ++j) {
            int idx = lane + 32 * j;
            unsigned long long h0 = hP[0][idx];
            unsigned long long h1 = hP[1][idx];
            unsigned long long h2 = hP[2][idx];
            unsigned long long h3 = hP[3][idx];
#pragma unroll
            for (int i = 0; i < 6; ++i) {
                ffma2(acc[i][0], w2[i][j], h0);
                ffma2(acc[i][1], w2[i][j], h1);
                ffma2(acc[i][2], w2[i][j], h2);
                ffma2(acc[i][3], w2[i][j], h3);
            }
        }

        // ---- combine k-halves, reduce over lanes (xor16, xor8) ----
        float s[6][4];
#pragma unroll
        for (int i = 0; i < 6; ++i)
#pragma unroll
            for (int b = 0; b < 4; ++b) {
                float l, h;
                asm("mov.b64 {%0,%1}, %2;" : "=f"(l), "=f"(h) : "l"(acc[i][b]));
                float v = l + h;
                v += __shfl_xor_sync(0xffffffffu, v, 16);
                v += __shfl_xor_sync(0xffffffffu, v, 8);
                s[i][b] = v;
            }
        if (lane < 8) {
#pragma unroll
            for (int i = 0; i < 6; ++i) {
                int cc = 6 * warp + i;
#pragma unroll
                for (int b = 0; b < 4; ++b)
                    red[(cc * BPG + b) * 8 + lane] = s[i][b];
            }
        }
        __syncthreads();

        // ---- gates (64 threads: 16 dims x 4 batches) ----
        if (tid < 64) {
            float gh[3];
#pragma unroll
            for (int g3 = 0; g3 < 3; ++g3) {
                const float* rp = &red[((g3 * 16 + dloc) * BPG + gb) * 8];
                float ssum = 0.f;
#pragma unroll
                for (int l = 0; l < 8; ++l) ssum += rp[l];
                gh[g3] = ssum;
            }
            float r = 1.f / (1.f + __expf(-(gir + gh[0])));
            float z = 1.f / (1.f + __expf(-(giz + gh[1])));
            float n = tanhf(gin + r * (gh[2] + my_bhn));
            float hnew = (1.f - z) * n + z * hold;
            hold = hnew;                                    // own h in register
            Hn[(d0 + dloc) * BPG + gb] = hnew;              // publish for peers
            g_rnn[((size_t)(b0 + gb) * Sm + t) * Dm + d0 + dloc] = hnew;

            // prefetch gi for t+1 (full-step DRAM latency cover)
            if (t + 1 < Sm) {
                const float* gp = g_gi
                    + ((size_t)(b0 + gb) * Sm + (t + 1)) * G3 + d0 + dloc;
                gir = __ldg(gp); giz = __ldg(gp + Dm); gin = __ldg(gp + 2 * Dm);
            }
        }

        // ---- early arrival: gate warps sync, tid0 fences + arrives ----
        if (tid < 64)
            asm volatile("bar.sync 1, 64;" ::: "memory");
        target += GCTA;
        if (tid == 0) {
            __threadfence();
            atomicAdd(cnt, 1u);
            while (ld_acq(cnt) < target) { }
        }
        __syncthreads();
    }
}

// ---------------------------------------------------------------------------
extern "C" void kernel_launch(void* const* d_in, const int* in_sizes, int n_in,
                              void* d_out, int out_size)
{
    const float* x   = (const float*)d_in[0];
    const float* Wi  = (const float*)d_in[1];
    const float* bi  = (const float*)d_in[2];
    const float* Wh  = (const float*)d_in[3];
    const float* bhn = (const float*)d_in[4];
    const float* Wo  = (const float*)d_in[5];
    const float* bo  = (const float*)d_in[6];
    float* out = (float*)d_out;

    void* gi_ptr = nullptr;
    void* rnn_ptr = nullptr;
    cudaGetSymbolAddress(&gi_ptr, g_gi);
    cudaGetSymbolAddress(&rnn_ptr, g_rnn);

    init_state<<<32, 256>>>();

    dim3 g1(G3 / 64, (Bm_ * Sm) / 128);
    tf32_gemm_bias<<<g1, 256>>>(x, Wi, bi, (float*)gi_ptr, Bm_ * Sm, G3, Dm);

    gru_scan<<<NBLK, NTHR>>>(Wh, bhn);

    dim3 g2(Dm / 64, (Bm_ * Sm) / 128);
    tf32_gemm_bias<<<g2, 256>>>((const float*)rnn_ptr, Wo, bo, out, Bm_ * Sm, Dm, Dm);
}